// round 11
// baseline (speedup 1.0000x reference)
#include <cuda_runtime.h>
#include <math.h>
#include <stdint.h>

// Causal depthwise conv1d, K=24, T=3000.
// y[b,c,t] = sum_{k=0..23} w[c,k] * x[b,c,t-23+k]
// w[c,k] = beta*exp(log(max(alpha,1e-6))*k)*(1 - u^2/2 + u^4/24), u=theta*k
//
// R11: R9 design extended to FOUR rows per CTA (batches b0+{0,4,8,12}),
//      all 4 TMAs issued upfront (prefetch depth 4), prologue + weight MUFU
//      amortized 4x, grid 4096. Compute core unchanged (scalar FFMA, R=12,
//      conflict-free 48B-stride LDS.128, in-loop broadcast weight LDS).
//      Static smem ~47.4KB -> 4 CTAs/SM.

#define KSZ 24
#define T_LEN 3000
#define R_OUT 12
#define NACT (T_LEN / R_OUT)   // 250 active compute threads
#define NTHREADS 256
#define PAD 24
#define NROWS 4
#define ROW_BYTES (T_LEN * 4)  // 12000, 16B multiple

__device__ __forceinline__ void mbar_wait(uint32_t mba, uint32_t parity) {
    uint32_t done;
    asm volatile(
        "{\n\t"
        ".reg .pred p;\n\t"
        "mbarrier.try_wait.parity.acquire.cta.shared::cta.b64 p, [%1], %2;\n\t"
        "selp.b32 %0, 1, 0, p;\n\t"
        "}"
        : "=r"(done) : "r"(mba), "r"(parity) : "memory");
    if (!done) {
        asm volatile(
            "{\n\t"
            ".reg .pred P1;\n\t"
            "WAIT_LOOP_%=:\n\t"
            "mbarrier.try_wait.parity.acquire.cta.shared::cta.b64 P1, [%0], %1, 0x989680;\n\t"
            "@P1 bra.uni WAIT_DONE_%=;\n\t"
            "bra.uni WAIT_LOOP_%=;\n\t"
            "WAIT_DONE_%=:\n\t"
            "}"
            :: "r"(mba), "r"(parity) : "memory");
    }
}

__device__ __forceinline__ void tma_row(uint32_t sdst, const float* src,
                                        uint32_t mba) {
    asm volatile("mbarrier.arrive.expect_tx.shared.b64 _, [%0], %1;"
                 :: "r"(mba), "r"((uint32_t)ROW_BYTES) : "memory");
    asm volatile(
        "cp.async.bulk.shared::cluster.global.mbarrier::complete_tx::bytes "
        "[%0], [%1], %2, [%3];"
        :: "r"(sdst), "l"(src), "r"((uint32_t)ROW_BYTES), "r"(mba)
        : "memory");
}

__device__ __forceinline__ void compute_row(const float* __restrict__ Sc,
                                            const float* __restrict__ sw,
                                            float* __restrict__ y,
                                            int rowbase, int tid) {
    // window: X[0..35] = Sc[12*tid .. 12*tid+35]
    // 9 LDS.128, lane stride 48B -> all 32 banks once per 8-lane phase.
    float X[R_OUT + KSZ];
    const float4* S4 = reinterpret_cast<const float4*>(&Sc[R_OUT * tid]);
#pragma unroll
    for (int j = 0; j < 9; j++) {
        float4 v = S4[j];
        X[4 * j + 0] = v.x; X[4 * j + 1] = v.y;
        X[4 * j + 2] = v.z; X[4 * j + 3] = v.w;
    }

    float acc[R_OUT];
#pragma unroll
    for (int j = 0; j < R_OUT; j++) acc[j] = 0.0f;

    const float4* sw4 = reinterpret_cast<const float4*>(sw);
#pragma unroll
    for (int g = 0; g < KSZ / 4; g++) {
        float4 wv = sw4[g];
        const int k0 = 4 * g;
#pragma unroll
        for (int j = 0; j < R_OUT; j++)
            acc[j] = fmaf(wv.x, X[j + 1 + k0 + 0], acc[j]);
#pragma unroll
        for (int j = 0; j < R_OUT; j++)
            acc[j] = fmaf(wv.y, X[j + 1 + k0 + 1], acc[j]);
#pragma unroll
        for (int j = 0; j < R_OUT; j++)
            acc[j] = fmaf(wv.z, X[j + 1 + k0 + 2], acc[j]);
#pragma unroll
        for (int j = 0; j < R_OUT; j++)
            acc[j] = fmaf(wv.w, X[j + 1 + k0 + 3], acc[j]);
    }

    float4* yo = reinterpret_cast<float4*>(y + rowbase + R_OUT * tid);
#pragma unroll
    for (int j = 0; j < 3; j++) {
        float4 o;
        o.x = acc[4 * j + 0]; o.y = acc[4 * j + 1];
        o.z = acc[4 * j + 2]; o.w = acc[4 * j + 3];
        yo[j] = o;
    }
}

__global__ __launch_bounds__(NTHREADS, 4)
void ssm4d_conv_kernel(const float* __restrict__ x,
                       const float* __restrict__ alpha,
                       const float* __restrict__ beta,
                       const float* __restrict__ theta,
                       float* __restrict__ y,
                       int C, int Bq)
{
    // Four buffers: S[q][0..23] = zeros, S[q][24+t] = x[row_q, t]
    // Identity: y[t] = sum_k w[k] * S[t + 1 + k]
    __shared__ __align__(16) float S[NROWS][PAD + T_LEN];   // 4*12096B
    __shared__ __align__(16) float sw[KSZ];
    __shared__ __align__(8)  unsigned long long mbar[NROWS];

    const int c   = blockIdx.x;
    const int b0  = blockIdx.y;        // rows: batches b0 + q*Bq, q=0..3
    const int tid = threadIdx.x;

    uint32_t mb[NROWS], sd[NROWS];
    int rowb[NROWS];
#pragma unroll
    for (int q = 0; q < NROWS; q++) {
        mb[q]  = (uint32_t)__cvta_generic_to_shared(&mbar[q]);
        sd[q]  = (uint32_t)__cvta_generic_to_shared(&S[q][PAD]);
        rowb[q] = ((b0 + q * Bq) * C + c) * T_LEN;
    }

    if (tid == 0) {
#pragma unroll
        for (int q = 0; q < NROWS; q++)
            asm volatile("mbarrier.init.shared.b64 [%0], 1;"
                         :: "r"(mb[q]) : "memory");
    }
    __syncthreads();

    // all four TMAs upfront: prefetch depth 4
    if (tid == 0) {
#pragma unroll
        for (int q = 0; q < NROWS; q++)
            tma_row(sd[q], x + rowb[q], mb[q]);
    }

    // overlap with TMA flight: pads + per-channel weights (once per 4 rows)
    if (tid < PAD / 4) {
#pragma unroll
        for (int q = 0; q < NROWS; q++)
            reinterpret_cast<float4*>(S[q])[tid] =
                make_float4(0.f, 0.f, 0.f, 0.f);
    }
    if (tid < KSZ) {
        float a  = alpha[c];
        float la = logf(fmaxf(a, 1e-6f));
        float d  = expf(la * (float)tid);
        float u  = theta[c] * (float)tid;
        float u2 = u * u;
        float ph = 1.0f - 0.5f * u2 + (u2 * u2) * (1.0f / 24.0f);
        sw[tid] = beta[c] * d * ph;
    }
    __syncthreads();   // pads + weights visible

#pragma unroll
    for (int q = 0; q < NROWS; q++) {
        mbar_wait(mb[q], 0u);
        if (tid < NACT) compute_row(S[q], sw, y, rowb[q], tid);
    }
}

extern "C" void kernel_launch(void* const* d_in, const int* in_sizes, int n_in,
                              void* d_out, int out_size)
{
    const float* x     = (const float*)d_in[0];
    const float* alpha = (const float*)d_in[1];
    const float* beta  = (const float*)d_in[2];
    const float* theta = (const float*)d_in[3];
    float* y = (float*)d_out;

    const int C = in_sizes[1];                 // 1024
    const int B = in_sizes[0] / (C * T_LEN);   // 16

    dim3 grid(C, B / NROWS);
    ssm4d_conv_kernel<<<grid, NTHREADS>>>(x, alpha, beta, theta, y, C,
                                          B / NROWS);
}

// round 12
// speedup vs baseline: 1.0349x; 1.0349x over previous
#include <cuda_runtime.h>
#include <math.h>
#include <stdint.h>

// Causal depthwise conv1d, K=24, T=3000.
// y[b,c,t] = sum_{k=0..23} w[c,k] * x[b,c,t-23+k]
// w[c,k] = beta*exp(log(max(alpha,1e-6))*k)*(1 - u^2/2 + u^4/24), u=theta*k
//
// R12: R9 (two rows per CTA, both TMAs upfront, scalar-FFMA R=12 core,
//      conflict-free 48B-stride LDS.128, in-loop broadcast weight LDS)
//      with reg cap relaxed (256,7): 36 regs instead of exactly 32, to
//      remove suspected local spills in the 2-row variant. Occ 87.5%.

#define KSZ 24
#define T_LEN 3000
#define R_OUT 12
#define NACT (T_LEN / R_OUT)   // 250 active compute threads
#define NTHREADS 256
#define PAD 24
#define ROW_BYTES (T_LEN * 4)  // 12000, 16B multiple

__device__ __forceinline__ void mbar_wait(uint32_t mba, uint32_t parity) {
    uint32_t done;
    asm volatile(
        "{\n\t"
        ".reg .pred p;\n\t"
        "mbarrier.try_wait.parity.acquire.cta.shared::cta.b64 p, [%1], %2;\n\t"
        "selp.b32 %0, 1, 0, p;\n\t"
        "}"
        : "=r"(done) : "r"(mba), "r"(parity) : "memory");
    if (!done) {
        asm volatile(
            "{\n\t"
            ".reg .pred P1;\n\t"
            "WAIT_LOOP_%=:\n\t"
            "mbarrier.try_wait.parity.acquire.cta.shared::cta.b64 P1, [%0], %1, 0x989680;\n\t"
            "@P1 bra.uni WAIT_DONE_%=;\n\t"
            "bra.uni WAIT_LOOP_%=;\n\t"
            "WAIT_DONE_%=:\n\t"
            "}"
            :: "r"(mba), "r"(parity) : "memory");
    }
}

__device__ __forceinline__ void tma_row(uint32_t sdst, const float* src,
                                        uint32_t mba) {
    asm volatile("mbarrier.arrive.expect_tx.shared.b64 _, [%0], %1;"
                 :: "r"(mba), "r"((uint32_t)ROW_BYTES) : "memory");
    asm volatile(
        "cp.async.bulk.shared::cluster.global.mbarrier::complete_tx::bytes "
        "[%0], [%1], %2, [%3];"
        :: "r"(sdst), "l"(src), "r"((uint32_t)ROW_BYTES), "r"(mba)
        : "memory");
}

__device__ __forceinline__ void compute_row(const float* __restrict__ Sc,
                                            const float* __restrict__ sw,
                                            float* __restrict__ y,
                                            int rowbase, int tid) {
    // window: X[0..35] = Sc[12*tid .. 12*tid+35]
    // 9 LDS.128, lane stride 48B -> all 32 banks once per 8-lane phase.
    float X[R_OUT + KSZ];
    const float4* S4 = reinterpret_cast<const float4*>(&Sc[R_OUT * tid]);
#pragma unroll
    for (int j = 0; j < 9; j++) {
        float4 v = S4[j];
        X[4 * j + 0] = v.x; X[4 * j + 1] = v.y;
        X[4 * j + 2] = v.z; X[4 * j + 3] = v.w;
    }

    float acc[R_OUT];
#pragma unroll
    for (int j = 0; j < R_OUT; j++) acc[j] = 0.0f;

    const float4* sw4 = reinterpret_cast<const float4*>(sw);
#pragma unroll
    for (int g = 0; g < KSZ / 4; g++) {
        float4 wv = sw4[g];
        const int k0 = 4 * g;
#pragma unroll
        for (int j = 0; j < R_OUT; j++)
            acc[j] = fmaf(wv.x, X[j + 1 + k0 + 0], acc[j]);
#pragma unroll
        for (int j = 0; j < R_OUT; j++)
            acc[j] = fmaf(wv.y, X[j + 1 + k0 + 1], acc[j]);
#pragma unroll
        for (int j = 0; j < R_OUT; j++)
            acc[j] = fmaf(wv.z, X[j + 1 + k0 + 2], acc[j]);
#pragma unroll
        for (int j = 0; j < R_OUT; j++)
            acc[j] = fmaf(wv.w, X[j + 1 + k0 + 3], acc[j]);
    }

    float4* yo = reinterpret_cast<float4*>(y + rowbase + R_OUT * tid);
#pragma unroll
    for (int j = 0; j < 3; j++) {
        float4 o;
        o.x = acc[4 * j + 0]; o.y = acc[4 * j + 1];
        o.z = acc[4 * j + 2]; o.w = acc[4 * j + 3];
        yo[j] = o;
    }
}

__global__ __launch_bounds__(NTHREADS, 7)
void ssm4d_conv_kernel(const float* __restrict__ x,
                       const float* __restrict__ alpha,
                       const float* __restrict__ beta,
                       const float* __restrict__ theta,
                       float* __restrict__ y,
                       int C, int Bh)
{
    // Two buffers: S[i][0..23] = zeros, S[i][24+t] = x[row_i, t]
    // Identity: y[t] = sum_k w[k] * S[t + 1 + k]
    __shared__ __align__(16) float S[2][PAD + T_LEN];
    __shared__ __align__(16) float sw[KSZ];
    __shared__ __align__(8)  unsigned long long mbar[2];

    const int c   = blockIdx.x;
    const int b0  = blockIdx.y;        // row pair: batches b0 and b0+Bh
    const int tid = threadIdx.x;
    const int row0 = (b0 * C + c) * T_LEN;
    const int row1 = ((b0 + Bh) * C + c) * T_LEN;

    const uint32_t mb0 = (uint32_t)__cvta_generic_to_shared(&mbar[0]);
    const uint32_t mb1 = (uint32_t)__cvta_generic_to_shared(&mbar[1]);
    const uint32_t sd0 = (uint32_t)__cvta_generic_to_shared(&S[0][PAD]);
    const uint32_t sd1 = (uint32_t)__cvta_generic_to_shared(&S[1][PAD]);

    if (tid == 0) {
        asm volatile("mbarrier.init.shared.b64 [%0], 1;" :: "r"(mb0) : "memory");
        asm volatile("mbarrier.init.shared.b64 [%0], 1;" :: "r"(mb1) : "memory");
    }
    __syncthreads();

    // both TMAs upfront: prefetch depth 2
    if (tid == 0) {
        tma_row(sd0, x + row0, mb0);
        tma_row(sd1, x + row1, mb1);
    }

    // overlap with TMA flight: pads + per-channel weights (once per 2 rows)
    if (tid < PAD / 4) {
        reinterpret_cast<float4*>(S[0])[tid] = make_float4(0.f, 0.f, 0.f, 0.f);
        reinterpret_cast<float4*>(S[1])[tid] = make_float4(0.f, 0.f, 0.f, 0.f);
    }
    if (tid < KSZ) {
        float a  = alpha[c];
        float la = logf(fmaxf(a, 1e-6f));
        float d  = expf(la * (float)tid);
        float u  = theta[c] * (float)tid;
        float u2 = u * u;
        float ph = 1.0f - 0.5f * u2 + (u2 * u2) * (1.0f / 24.0f);
        sw[tid] = beta[c] * d * ph;
    }
    __syncthreads();   // pads + weights visible

    mbar_wait(mb0, 0u);
    if (tid < NACT) compute_row(S[0], sw, y, row0, tid);

    mbar_wait(mb1, 0u);
    if (tid < NACT) compute_row(S[1], sw, y, row1, tid);
}

extern "C" void kernel_launch(void* const* d_in, const int* in_sizes, int n_in,
                              void* d_out, int out_size)
{
    const float* x     = (const float*)d_in[0];
    const float* alpha = (const float*)d_in[1];
    const float* beta  = (const float*)d_in[2];
    const float* theta = (const float*)d_in[3];
    float* y = (float*)d_out;

    const int C = in_sizes[1];                 // 1024
    const int B = in_sizes[0] / (C * T_LEN);   // 16

    dim3 grid(C, B / 2);
    ssm4d_conv_kernel<<<grid, NTHREADS>>>(x, alpha, beta, theta, y, C, B / 2);
}